// round 1
// baseline (speedup 1.0000x reference)
#include <cuda_runtime.h>

#define NB 8192
#define NT 1024
#define OUTROW 6150   // (NT+1)*6 floats per robot row

__device__ __forceinline__ float softplusf(float x) {
    // matches jax.nn.softplus to fp32 rounding for the value ranges here
    return (x > 20.0f) ? x : log1pf(expf(x));
}

__device__ __forceinline__ float sgnf(float v) {
    return (v > 0.0f) ? 1.0f : ((v < 0.0f) ? -1.0f : 0.0f);
}

__global__ void __launch_bounds__(32)
omni_sim_kernel(const float* __restrict__ init,
                const float* __restrict__ cmd,
                const float* __restrict__ com,
                const float* __restrict__ pI,
                const float* __restrict__ pG,
                const float* __restrict__ pT,
                const float* __restrict__ pDv,
                const float* __restrict__ pDc,
                float* __restrict__ out)
{
    int b = blockIdx.x * 32 + threadIdx.x;
    if (b >= NB) return;

    const float DT      = 0.016f;
    const float PI_F    = 3.14159265358979323846f;
    const float TWOPI_F = 6.28318530717958647692f;

    const float inertia = softplusf(pI[0]) + 1e-4f;
    const float gain    = softplusf(pG[0]);
    const float grip    = softplusf(pT[0]);
    const float dv0 = softplusf(pDv[0]);
    const float dv1 = softplusf(pDv[1]);
    const float dv2 = softplusf(pDv[2]);
    const float dc0 = softplusf(pDc[0]);
    const float dc1 = softplusf(pDc[1]);
    const float dc2 = softplusf(pDc[2]);
    const float dxo = com[0];
    const float dyo = com[1];
    const float invM = 1.0f / 2.8f;
    const float invI = 1.0f / inertia;

    // G = FORCE_MATRIX @ FORCE_MATRIX^T (sparse; off-diagonals G01=G02=0)
    const float A00 = gain * 2.6736481776669304f + grip;
    const float A11 = gain * 1.3263518223330696f + grip;
    const float A12 = gain * (-0.02570176974357713f);
    const float A22 = gain * 0.0324f + grip;

    // Load initial state (6 floats, 8B-aligned)
    const float2* i2 = (const float2*)(init + (size_t)b * 6);
    float2 s0 = i2[0], s1 = i2[1], s2 = i2[2];
    float x = s0.x, y = s0.y, th = s1.x, vx = s1.y, vy = s2.x, om = s2.y;

    // Emit t=0 row = initial state
    float2* o2 = (float2*)(out + (size_t)b * OUTROW);
    o2[0] = s0; o2[1] = s1; o2[2] = s2;
    o2 += 3;

    // Command row for this robot: 1024*3 floats, 16B-aligned base
    const float4* c4 = (const float4*)(cmd + (size_t)b * (NT * 3));

#define STEP(C0, C1, C2, O) do {                                             \
    float s_, c_; __sincosf(th, &s_, &c_);                                   \
    float vxb = fmaf(vx, c_,  vy * s_);                                      \
    float vyb = fmaf(vy, c_, -vx * s_);                                      \
    float d0 = (C0) - vxb, d1 = (C1) - vyb, d2 = (C2) - om;                  \
    float F0 = fmaf(A00, d0, fmaf(-dv0, vxb, -dc0 * sgnf(vxb)));             \
    float F1 = fmaf(A11, d1, fmaf(A12, d2, fmaf(-dv1, vyb, -dc1 * sgnf(vyb))));\
    float F2 = fmaf(A12, d1, fmaf(A22, d2, fmaf(-dv2, om,  -dc2 * sgnf(om))));\
    float tau = F2 - (dxo * F1 - dyo * F0);                                  \
    float ax = F0 * invM, ay = F1 * invM, al = tau * invI;                   \
    float om2 = om * om;                                                     \
    float axb = fmaf(-al, dyo, fmaf(-om2, dxo, ax));                         \
    float ayb = fmaf( al, dxo, fmaf(-om2, dyo, ay));                         \
    float axw = fmaf(axb, c_, -ayb * s_);                                    \
    float ayw = fmaf(axb, s_,  ayb * c_);                                    \
    vx = fmaf(axw, DT, vx);                                                  \
    vy = fmaf(ayw, DT, vy);                                                  \
    om = fmaf(al,  DT, om);                                                  \
    x  = fmaf(vx, DT, x);                                                    \
    y  = fmaf(vy, DT, y);                                                    \
    th = fmaf(om, DT, th);                                                   \
    th = (th >  PI_F) ? th - TWOPI_F : th;                                   \
    th = (th < -PI_F) ? th + TWOPI_F : th;                                   \
    o2[(O)+0] = make_float2(x, y);                                           \
    o2[(O)+1] = make_float2(th, vx);                                         \
    o2[(O)+2] = make_float2(vy, om);                                         \
} while (0)

    float4 ca = c4[0], cb = c4[1], cc = c4[2];

#pragma unroll 1
    for (int tb = 0; tb < NT; tb += 4) {
        float4 na = ca, nb = cb, nc = cc;
        if (tb + 4 < NT) {  // prefetch next 4 steps' commands
            na = c4[3]; nb = c4[4]; nc = c4[5];
        }
        c4 += 3;

        STEP(ca.x, ca.y, ca.z, 0);
        STEP(ca.w, cb.x, cb.y, 3);
        STEP(cb.z, cb.w, cc.x, 6);
        STEP(cc.y, cc.z, cc.w, 9);

        o2 += 12;
        ca = na; cb = nb; cc = nc;
    }
#undef STEP
}

extern "C" void kernel_launch(void* const* d_in, const int* in_sizes, int n_in,
                              void* d_out, int out_size)
{
    const float* init = (const float*)d_in[0];  // (8192, 6)
    const float* cmd  = (const float*)d_in[1];  // (8192, 1024, 3)
    const float* com  = (const float*)d_in[2];  // (2,)
    const float* pI   = (const float*)d_in[3];  // scalar
    const float* pG   = (const float*)d_in[4];  // scalar
    const float* pT   = (const float*)d_in[5];  // scalar
    const float* pDv  = (const float*)d_in[6];  // (3,)
    const float* pDc  = (const float*)d_in[7];  // (3,)
    float* out = (float*)d_out;                 // (8192, 1025, 6)

    dim3 grid((NB + 31) / 32);
    dim3 block(32);
    omni_sim_kernel<<<grid, block>>>(init, cmd, com, pI, pG, pT, pDv, pDc, out);
}

// round 3
// speedup vs baseline: 1.2699x; 1.2699x over previous
#include <cuda_runtime.h>

#define NB 8192
#define NT 1024
#define K  16
#define NTILES (NT / K)        // 64
#define OUTROW 6150            // (NT+1)*6 floats per robot
#define CMDROW (NT * 3)        // 3072 floats per robot
#define CPT (K * 3)            // 48 cmd floats per robot per tile
#define SPT (K * 6)            // 96 state floats per robot per tile
#define F2PT (SPT / 2)         // 48 float2 per robot per tile
#define STRIDE_ST 98           // padded smem state row (floats)

__device__ __forceinline__ float softplusf(float x) {
    return (x > 20.0f) ? x : log1pf(expf(x));
}
__device__ __forceinline__ float sgnf(float v) {
    return (v > 0.0f) ? 1.0f : ((v < 0.0f) ? -1.0f : 0.0f);
}

__global__ void __launch_bounds__(32)
omni_sim_kernel(const float* __restrict__ init,
                const float* __restrict__ cmd,
                const float* __restrict__ com,
                const float* __restrict__ pI,
                const float* __restrict__ pG,
                const float* __restrict__ pT,
                const float* __restrict__ pDv,
                const float* __restrict__ pDc,
                float* __restrict__ out)
{
    __shared__ float s_cmd[2][32 * CPT];     // 2 x 6 KB, double-buffered
    __shared__ float s_st[32 * STRIDE_ST];   // 12.25 KB state staging

    const int lane = threadIdx.x;
    const int b0   = blockIdx.x * 32;
    const int b    = b0 + lane;

    const float DT      = 0.016f;
    const float PI_F    = 3.14159265358979323846f;
    const float TWOPI_F = 6.28318530717958647692f;

    const float inertia = softplusf(pI[0]) + 1e-4f;
    const float gain    = softplusf(pG[0]);
    const float grip    = softplusf(pT[0]);
    const float dv0 = softplusf(pDv[0]);
    const float dv1 = softplusf(pDv[1]);
    const float dv2 = softplusf(pDv[2]);
    const float dc0 = softplusf(pDc[0]);
    const float dc1 = softplusf(pDc[1]);
    const float dc2 = softplusf(pDc[2]);
    const float dxo = com[0];
    const float dyo = com[1];
    const float invM = 1.0f / 2.8f;
    const float invI = 1.0f / inertia;

    // A = gain * (M M^T) + grip * I   (M M^T sparse: G01=G02=0 for these angles)
    const float A00 = gain * 2.6736481776669304f + grip;
    const float A11 = gain * 1.3263518223330696f + grip;
    const float A12 = gain * (-0.02570176974357713f);
    const float A22 = gain * 0.0324f + grip;

    // Initial state + t=0 output row (one-time, uncoalesced is fine)
    const float2* i2 = (const float2*)(init + (size_t)b * 6);
    float2 s0 = i2[0], s1 = i2[1], s2 = i2[2];
    float x = s0.x, y = s0.y, th = s1.x, vx = s1.y, vy = s2.x, om = s2.y;
    {
        float2* o2 = (float2*)(out + (size_t)b * OUTROW);
        o2[0] = s0; o2[1] = s1; o2[2] = s2;
    }

    // Cooperative cmd-load offsets (linear index e = i*32+lane over 384 float4s)
    const float* cmdbase = cmd + (size_t)b0 * CMDROW;
    int pf_goff[12], pf_soff[12];
#pragma unroll
    for (int i = 0; i < 12; i++) {
        int e = i * 32 + lane;
        int r = e / 12;
        int j = e - r * 12;
        pf_goff[i] = r * CMDROW + j * 4;   // gmem float offset within tile slice
        pf_soff[i] = r * CPT    + j * 4;   // smem float offset
    }

    // Preload tile 0 commands
#pragma unroll
    for (int i = 0; i < 12; i++) {
        float4 v = *(const float4*)(cmdbase + pf_goff[i]);
        *(float4*)(&s_cmd[0][pf_soff[i]]) = v;
    }
    __syncwarp();

    float* myst = &s_st[lane * STRIDE_ST];

    for (int tile = 0; tile < NTILES; ++tile) {
        const int buf = tile & 1;

        // Prefetch next tile's commands into registers (overlaps compute)
        float4 pf[12];
        if (tile + 1 < NTILES) {
            const float* src = cmdbase + (tile + 1) * CPT;
#pragma unroll
            for (int i = 0; i < 12; i++)
                pf[i] = *(const float4*)(src + pf_goff[i]);
        }

        // ── Compute K steps ──
        const float* mycmd = &s_cmd[buf][lane * CPT];
#pragma unroll
        for (int s = 0; s < K; s++) {
            float C0 = mycmd[3 * s + 0];
            float C1 = mycmd[3 * s + 1];
            float C2 = mycmd[3 * s + 2];

            float s_, c_; __sincosf(th, &s_, &c_);
            float vxb = fmaf(vx, c_,  vy * s_);
            float vyb = fmaf(vy, c_, -vx * s_);
            float d0 = C0 - vxb, d1 = C1 - vyb, d2 = C2 - om;
            float F0 = fmaf(A00, d0, fmaf(-dv0, vxb, -dc0 * sgnf(vxb)));
            float F1 = fmaf(A11, d1, fmaf(A12, d2, fmaf(-dv1, vyb, -dc1 * sgnf(vyb))));
            float F2 = fmaf(A12, d1, fmaf(A22, d2, fmaf(-dv2, om,  -dc2 * sgnf(om))));
            float tau = F2 - (dxo * F1 - dyo * F0);
            float ax = F0 * invM, ay = F1 * invM, al = tau * invI;
            float om2 = om * om;
            float axb = fmaf(-al, dyo, fmaf(-om2, dxo, ax));
            float ayb = fmaf( al, dxo, fmaf(-om2, dyo, ay));
            float axw = fmaf(axb, c_, -ayb * s_);
            float ayw = fmaf(axb, s_,  ayb * c_);
            vx = fmaf(axw, DT, vx);
            vy = fmaf(ayw, DT, vy);
            om = fmaf(al,  DT, om);
            x  = fmaf(vx, DT, x);
            y  = fmaf(vy, DT, y);
            th = fmaf(om, DT, th);
            th = (th >  PI_F) ? th - TWOPI_F : th;
            th = (th < -PI_F) ? th + TWOPI_F : th;

            myst[6 * s + 0] = x;
            myst[6 * s + 1] = y;
            myst[6 * s + 2] = th;
            myst[6 * s + 3] = vx;
            myst[6 * s + 4] = vy;
            myst[6 * s + 5] = om;
        }
        __syncwarp();

        // ── Cooperative coalesced store of the state tile (float2 units) ──
        {
            float*       gp = out + (size_t)b0 * OUTROW + 6 + tile * SPT + 2 * lane;
            const float* sp = s_st + 2 * lane;   // r=0, j=lane to start
            int j = lane;
#pragma unroll 6
            for (int i = 0; i < 48; i++) {
                float2 v = *(const float2*)sp;
                *(float2*)gp = v;
                j += 32;
                bool w = (j >= F2PT);
                j = w ? j - F2PT : j;
                gp += w ? (OUTROW - 32) : 64;       // Δr*OUTROW + 2Δj
                sp += w ? (STRIDE_ST - 32) : 64;    // Δr*STRIDE_ST + 2Δj
            }
        }
        __syncwarp();

        // ── Fill the other cmd buffer from prefetch registers ──
        if (tile + 1 < NTILES) {
#pragma unroll
            for (int i = 0; i < 12; i++)
                *(float4*)(&s_cmd[buf ^ 1][pf_soff[i]]) = pf[i];
            __syncwarp();
        }
    }
}

extern "C" void kernel_launch(void* const* d_in, const int* in_sizes, int n_in,
                              void* d_out, int out_size)
{
    const float* init = (const float*)d_in[0];  // (8192, 6)
    const float* cmd  = (const float*)d_in[1];  // (8192, 1024, 3)
    const float* com  = (const float*)d_in[2];  // (2,)
    const float* pI   = (const float*)d_in[3];
    const float* pG   = (const float*)d_in[4];
    const float* pT   = (const float*)d_in[5];
    const float* pDv  = (const float*)d_in[6];  // (3,)
    const float* pDc  = (const float*)d_in[7];  // (3,)
    float* out = (float*)d_out;                 // (8192, 1025, 6)

    omni_sim_kernel<<<NB / 32, 32>>>(init, cmd, com, pI, pG, pT, pDv, pDc, out);
}